// round 13
// baseline (speedup 1.0000x reference)
#include <cuda_runtime.h>
#include <cuda_fp16.h>
#include <cstdint>
#include <math.h>

// DataTransformer via mma.sync fp16 (fp32 accum), A-fragment reuse across t:
//   out[r,e] = sum_t softmax_t(cos(x_r,p_t)) * (x_r . W_t[e,:] + b_t[e]) + x[r,e]
// Loop order: kh (K-half) outer, t inner; warp's A frags for one K-half live in
// registers across all 8 transforms. W streamed as 16 8KB tiles via 5-buf ring.
// CTA tile: 128 rows x 64 cols, 256 threads, warp grid 4x2 (tile 32x32). 2 CTAs/SM.

#define D_DIM   128
#define T_DIM   8
#define MTILE   128
#define NTILE   64
#define THREADS 256
#define NROWS   65536

// fp16 W scratch (static __device__ array: allowed scratch form)
__device__ __half g_whi[T_DIM * D_DIM * D_DIM];

// ---- smem layout (bytes) ----
// x tile: 256 B rows + XOR-of-16B-chunk swizzle (c in [0,16))
// W tiles: 64 rows x 64 cols fp16 = 128 B rows, 8 chunks (c in [0,8)), 5-buffer ring
#define OFF_X    0u         // 32768
#define OFF_W    32768u     // 5 x 8192 = 40960
#define OFF_P    73728u     // 4096
#define OFF_B    77824u     // 2048
#define OFF_SIM  79872u     // 128*9*4 = 4608
#define OFF_PN2  84480u     // 32
#define SMEM_TOTAL 84512

__device__ __forceinline__ uint32_t smem_u32(const void* p) {
    uint32_t a;
    asm("{ .reg .u64 t; cvta.to.shared.u64 t, %1; cvt.u32.u64 %0, t; }" : "=r"(a) : "l"(p));
    return a;
}

#define CP_ASYNC16(dst, src) \
    asm volatile("cp.async.cg.shared.global [%0], [%1], 16;" :: "r"(dst), "l"(src) : "memory")
#define CP_COMMIT() asm volatile("cp.async.commit_group;" ::: "memory")
#define CP_WAITG(n) asm volatile("cp.async.wait_group %0;" :: "n"(n) : "memory")

#define LDM4(r0, r1, r2, r3, addr) \
    asm volatile("ldmatrix.sync.aligned.m8n8.x4.shared.b16 {%0,%1,%2,%3}, [%4];" \
        : "=r"(r0), "=r"(r1), "=r"(r2), "=r"(r3) : "r"(addr))

#define MMA16816(d, a0, a1, a2, a3, b0, b1) \
    asm volatile("mma.sync.aligned.m16n8k16.row.col.f32.f16.f16.f32 " \
        "{%0,%1,%2,%3}, {%4,%5,%6,%7}, {%8,%9}, {%0,%1,%2,%3};" \
        : "+f"((d)[0]), "+f"((d)[1]), "+f"((d)[2]), "+f"((d)[3]) \
        : "r"(a0), "r"(a1), "r"(a2), "r"(a3), "r"(b0), "r"(b1))

// x tile swizzle: 256 B rows, chunk c in [0,16)
__device__ __forceinline__ uint32_t swzX(int r, int c) {
    return (uint32_t)(r * 256 + ((c ^ (r & 7)) << 4));
}
// W tile swizzle: 128 B rows, chunk c in [0,8)
__device__ __forceinline__ uint32_t swzW(int r, int c) {
    return (uint32_t)(r * 128 + ((c ^ (r & 7)) << 4));
}

// ===================== Kernel 1: W fp32 -> fp16 preconvert (tiny) =====================
__global__ void conv_kernel(const float* __restrict__ W)
{
    const int W4 = T_DIM * D_DIM * D_DIM / 4;   // 32768 float4
    int i = blockIdx.x * blockDim.x + threadIdx.x;
    if (i < W4) {
        float4 v = reinterpret_cast<const float4*>(W)[i];
        uint32_t hw[4];
        float vf[4] = {v.x, v.y, v.z, v.w};
#pragma unroll
        for (int e = 0; e < 4; e++)
            hw[e] = (uint32_t)__half_as_ushort(__float2half_rn(vf[e]));
        reinterpret_cast<uint2*>(g_whi)[i] =
            make_uint2(hw[0] | (hw[1] << 16), hw[2] | (hw[3] << 16));
    }
}

// ===================== Kernel 2: GEMM + gating + fold =====================
// Stream tile idx = kh*8 + t (64 N-rows x 64 K-cols of W_t), 512 16B chunks.
__device__ __forceinline__ void issue_w_tile(uint32_t sb, int buf, int idx, int nbase, int tid)
{
    const int kh = idx >> 3, t = idx & 7;
    const size_t base = (size_t)t * (D_DIM * D_DIM) + (size_t)nbase * D_DIM + kh * 64;
    const uint32_t dst0 = sb + OFF_W + (uint32_t)buf * 8192u;
#pragma unroll
    for (int k = 0; k < 2; k++) {
        int ci = tid + k * THREADS;          // 0..511
        int r = ci >> 3, c = ci & 7;
        CP_ASYNC16(dst0 + swzW(r, c), g_whi + base + (size_t)r * D_DIM + c * 8);
    }
}

__global__ void __launch_bounds__(THREADS, 2)
dt_mma_kernel(const float* __restrict__ x,
              const float* __restrict__ b,
              const float* __restrict__ p,
              float* __restrict__ out)
{
    extern __shared__ char smem[];
    const uint32_t sb = smem_u32(smem);
    const int tid  = threadIdx.x;
    const int wid  = tid >> 5;
    const int lane = tid & 31;
    const int mblk = blockIdx.x >> 1;
    const int nblk = blockIdx.x & 1;
    const int row0 = mblk * MTILE;
    const int nbase = nblk * NTILE;

    float* s_p   = reinterpret_cast<float*>(smem + OFF_P);
    float* s_b   = reinterpret_cast<float*>(smem + OFF_B);
    float* s_sim = reinterpret_cast<float*>(smem + OFF_SIM);
    float* s_pn2 = reinterpret_cast<float*>(smem + OFF_PN2);

    // W ring prologue: tiles 0..3 into bufs 0..3 (they fly during convert+gating)
    issue_w_tile(sb, 0, 0, nbase, tid); CP_COMMIT();
    issue_w_tile(sb, 1, 1, nbase, tid); CP_COMMIT();
    issue_w_tile(sb, 2, 2, nbase, tid); CP_COMMIT();
    issue_w_tile(sb, 3, 3, nbase, tid); CP_COMMIT();

    // p (full) and b (this CTA's 64-col slice) to smem
#pragma unroll
    for (int i = tid; i < T_DIM * D_DIM; i += THREADS) s_p[i] = p[i];
#pragma unroll
    for (int i = tid; i < T_DIM * NTILE; i += THREADS)
        s_b[i] = b[(i >> 6) * D_DIM + nbase + (i & 63)];

    // x tile: fp32 gmem -> fp16 swizzled smem (2048 16B chunks, 8 per thread)
#pragma unroll
    for (int k = 0; k < 8; k++) {
        int ci = tid + k * THREADS;
        int r = ci >> 4, c = ci & 15;
        const float4* src = reinterpret_cast<const float4*>(
            x + (size_t)(row0 + r) * D_DIM + c * 8);
        float4 v0 = src[0], v1 = src[1];
        uint32_t hw[4];
        hw[0] = (uint32_t)__half_as_ushort(__float2half_rn(v0.x))
              | ((uint32_t)__half_as_ushort(__float2half_rn(v0.y)) << 16);
        hw[1] = (uint32_t)__half_as_ushort(__float2half_rn(v0.z))
              | ((uint32_t)__half_as_ushort(__float2half_rn(v0.w)) << 16);
        hw[2] = (uint32_t)__half_as_ushort(__float2half_rn(v1.x))
              | ((uint32_t)__half_as_ushort(__float2half_rn(v1.y)) << 16);
        hw[3] = (uint32_t)__half_as_ushort(__float2half_rn(v1.z))
              | ((uint32_t)__half_as_ushort(__float2half_rn(v1.w)) << 16);
        *reinterpret_cast<uint4*>(smem + OFF_X + swzX(r, c)) =
            make_uint4(hw[0], hw[1], hw[2], hw[3]);
    }

    __syncthreads();   // s_p visible for gating

    // ---- Gating (exact fp32; overlaps W cp.async) ----
    if (tid < T_DIM) {
        float pn2 = 0.f;
        const float4* pr = reinterpret_cast<const float4*>(s_p + tid * D_DIM);
#pragma unroll 8
        for (int i = 0; i < 32; i++) {
            float4 pv = pr[i];
            pn2 += pv.x * pv.x + pv.y * pv.y + pv.z * pv.z + pv.w * pv.w;
        }
        s_pn2[tid] = pn2;
    }
    float dots[T_DIM], xn2 = 0.f;
    if (tid < MTILE) {
#pragma unroll
        for (int t = 0; t < T_DIM; t++) dots[t] = 0.f;
        const float4* xr = reinterpret_cast<const float4*>(x + (size_t)(row0 + tid) * D_DIM);
#pragma unroll 4
        for (int i = 0; i < 32; i++) {
            float4 v = xr[i];
            xn2 += v.x * v.x + v.y * v.y + v.z * v.z + v.w * v.w;
#pragma unroll
            for (int t = 0; t < T_DIM; t++) {
                float4 pv = *reinterpret_cast<const float4*>(s_p + t * D_DIM + i * 4);
                dots[t] += v.x * pv.x + v.y * pv.y + v.z * pv.z + v.w * pv.w;
            }
        }
    }
    __syncthreads();   // s_pn2 ready
    if (tid < MTILE) {
        float xn = sqrtf(xn2);
        float cosv[T_DIM], m = -1e30f;
#pragma unroll
        for (int t = 0; t < T_DIM; t++) {
            cosv[t] = dots[t] / (xn * sqrtf(s_pn2[t]));
            m = fmaxf(m, cosv[t]);
        }
        float ev[T_DIM], sum = 0.f;
#pragma unroll
        for (int t = 0; t < T_DIM; t++) { ev[t] = expf(cosv[t] - m); sum += ev[t]; }
        float inv = 1.f / sum;
#pragma unroll
        for (int t = 0; t < T_DIM; t++) s_sim[tid * 9 + t] = ev[t] * inv;
    }

    // ---- Warp tiling: 4(M) x 2(N) grid, warp tile 32x32 ----
    const int wm = wid & 3, wn = wid >> 2;
    const int mbw = wm * 32, nbw = wn * 32;

    const uint32_t arowb = (uint32_t)((mbw + (lane & 15)) * 256);
    const int     achnk  = lane >> 4;
    const uint32_t browb = (uint32_t)((nbw + (lane & 7) + ((lane >> 4) << 3)) * 128);
    const int     bchnk  = (lane >> 3) & 1;
    const int     bank   = lane & 7;             // == row&7 for both lane->row maps
    const int rql = lane >> 2;
    const int cpl = (lane & 3) * 2;

    float acc[2][4][4];
#pragma unroll
    for (int i = 0; i < 2; i++)
#pragma unroll
        for (int j = 0; j < 4; j++)
#pragma unroll
            for (int e = 0; e < 4; e++) acc[i][j][e] = 0.f;

    uint32_t ah[4][8];   // A fragments for one K-half: 4 k-steps x (2 frags of 4 regs)

#pragma unroll 1
    for (int i = 0; i < 16; i++) {
        // wait for tile i (commits so far: 4 + min(i,12))
        if (i < 13)      { CP_WAITG(3); }
        else if (i == 13){ CP_WAITG(2); }
        else if (i == 14){ CP_WAITG(1); }
        else             { CP_WAITG(0); }
        __syncthreads();   // tile i visible to all; iter i-1 compute fully drained

        // refill ring: tile i+4 into buf (i+4)%5 (held tile i-1, now consumed)
        if (i < 12) {
            issue_w_tile(sb, (i + 4) % 5, i + 4, nbase, tid);
            CP_COMMIT();
        }

        // load A fragments at K-half boundary (once per 8 tiles)
        if ((i & 7) == 0) {
            const int kh = i >> 3;
#pragma unroll
            for (int k = 0; k < 4; k++) {
                const int kc = 2 * (kh * 4 + k) + achnk;
                const uint32_t aoff = arowb + (uint32_t)((kc ^ bank) << 4);
                LDM4(ah[k][0], ah[k][1], ah[k][2], ah[k][3], sb + OFF_X + aoff);
                LDM4(ah[k][4], ah[k][5], ah[k][6], ah[k][7], sb + OFF_X + aoff + 16u * 256u);
            }
        }

        // compute tile i: t = i&7
        const uint32_t wbuf = sb + OFF_W + (uint32_t)(i % 5) * 8192u;
        float y[2][4][4];
#pragma unroll
        for (int a = 0; a < 2; a++)
#pragma unroll
            for (int j = 0; j < 4; j++)
#pragma unroll
                for (int e = 0; e < 4; e++) y[a][j][e] = 0.f;

#pragma unroll
        for (int k = 0; k < 4; k++) {
            const uint32_t boff = browb + (uint32_t)((((2 * k + bchnk)) ^ bank) << 4);
            uint32_t bh0, bh1, bh2, bh3, bh4, bh5, bh6, bh7;
            LDM4(bh0, bh1, bh2, bh3, wbuf + boff);
            LDM4(bh4, bh5, bh6, bh7, wbuf + boff + 16u * 128u);

            MMA16816(y[0][0], ah[k][0], ah[k][1], ah[k][2], ah[k][3], bh0, bh1);
            MMA16816(y[0][1], ah[k][0], ah[k][1], ah[k][2], ah[k][3], bh2, bh3);
            MMA16816(y[0][2], ah[k][0], ah[k][1], ah[k][2], ah[k][3], bh4, bh5);
            MMA16816(y[0][3], ah[k][0], ah[k][1], ah[k][2], ah[k][3], bh6, bh7);
            MMA16816(y[1][0], ah[k][4], ah[k][5], ah[k][6], ah[k][7], bh0, bh1);
            MMA16816(y[1][1], ah[k][4], ah[k][5], ah[k][6], ah[k][7], bh2, bh3);
            MMA16816(y[1][2], ah[k][4], ah[k][5], ah[k][6], ah[k][7], bh4, bh5);
            MMA16816(y[1][3], ah[k][4], ah[k][5], ah[k][6], ah[k][7], bh6, bh7);
        }

        // fold: acc += sim_t * (y + bias)   (bias only on the kh=0 pass)
        {
            const int t = i & 7;
            const bool wbias = (i < 8);
#pragma unroll
            for (int mt = 0; mt < 2; mt++) {
                const int rloc = mbw + mt * 16 + rql;
                const float s0 = s_sim[rloc * 9 + t];
                const float s1 = s_sim[(rloc + 8) * 9 + t];
#pragma unroll
                for (int nt = 0; nt < 4; nt++) {
                    const int c = nbw + nt * 8 + cpl;
                    const float bb0 = wbias ? s_b[t * NTILE + c]     : 0.f;
                    const float bb1 = wbias ? s_b[t * NTILE + c + 1] : 0.f;
                    acc[mt][nt][0] = fmaf(s0, y[mt][nt][0] + bb0, acc[mt][nt][0]);
                    acc[mt][nt][1] = fmaf(s0, y[mt][nt][1] + bb1, acc[mt][nt][1]);
                    acc[mt][nt][2] = fmaf(s1, y[mt][nt][2] + bb0, acc[mt][nt][2]);
                    acc[mt][nt][3] = fmaf(s1, y[mt][nt][3] + bb1, acc[mt][nt][3]);
                }
            }
        }
    }

    // ---- Epilogue: residual (exact fp32 x from gmem) + store ----
#pragma unroll
    for (int mt = 0; mt < 2; mt++) {
        const int rg0 = row0 + mbw + mt * 16 + rql;
        const int rg1 = rg0 + 8;
#pragma unroll
        for (int nt = 0; nt < 4; nt++) {
            const int c = nbase + nbw + nt * 8 + cpl;
            float2 xv0 = *reinterpret_cast<const float2*>(x + (size_t)rg0 * D_DIM + c);
            float2 o0  = make_float2(acc[mt][nt][0] + xv0.x, acc[mt][nt][1] + xv0.y);
            *reinterpret_cast<float2*>(out + (size_t)rg0 * D_DIM + c) = o0;
            float2 xv1 = *reinterpret_cast<const float2*>(x + (size_t)rg1 * D_DIM + c);
            float2 o1  = make_float2(acc[mt][nt][2] + xv1.x, acc[mt][nt][3] + xv1.y);
            *reinterpret_cast<float2*>(out + (size_t)rg1 * D_DIM + c) = o1;
        }
    }
}

extern "C" void kernel_launch(void* const* d_in, const int* in_sizes, int n_in,
                              void* d_out, int out_size)
{
    (void)n_in; (void)out_size;
    const float* x = (const float*)d_in[0];   // [B,S,D]
    const float* W = (const float*)d_in[1];   // [T,D,D]
    const float* b = (const float*)d_in[2];   // [T,D]
    const float* p = (const float*)d_in[3];   // [T,1,D]
    float* out = (float*)d_out;

    const int nrows = in_sizes[0] / D_DIM;    // 65536
    const int grid  = (nrows / MTILE) * 2;    // 1024

    conv_kernel<<<128, 256>>>(W);

    cudaFuncSetAttribute(dt_mma_kernel,
                         cudaFuncAttributeMaxDynamicSharedMemorySize, SMEM_TOTAL);
    dt_mma_kernel<<<grid, THREADS, SMEM_TOTAL>>>(x, b, p, out);
}

// round 14
// speedup vs baseline: 1.0645x; 1.0645x over previous
#include <cuda_runtime.h>
#include <cuda_fp16.h>
#include <cstdint>
#include <math.h>

// DataTransformer via mma.sync fp16 (fp32 accum), t-PAIRED single-pass GEMM:
// per k-step: A frags loaded once, used by two transforms (16-MMA runs / 6 LDM4).
//   out[r,e] = sum_t softmax_t(cos(x_r,p_t)) * (x_r . W_t[e,:] + b_t[e]) + x[r,e]
// CTA tile: 128 rows x 64 cols, 256 threads, warp grid 4x2 (tile 32x32). 2 CTAs/SM.

#define D_DIM   128
#define T_DIM   8
#define MTILE   128
#define NTILE   64
#define THREADS 256
#define NROWS   65536

// fp16 W scratch (static __device__ array: allowed scratch form)
__device__ __half g_whi[T_DIM * D_DIM * D_DIM];

// ---- smem layout (bytes). Tiles: 256 B rows + XOR-of-16B-chunk swizzle ----
#define OFF_X    0u         // 128x128 fp16 = 32768
#define OFF_W    32768u     // 2 pair-buffers x 32768 (2 t-tiles of 16384) = 65536
#define OFF_P    98304u     // 4096
#define OFF_B    102400u    // 2048
#define OFF_SIM  104448u    // 128*9*4 = 4608
#define OFF_PN2  109056u    // 32
#define SMEM_TOTAL 109088

__device__ __forceinline__ uint32_t smem_u32(const void* p) {
    uint32_t a;
    asm("{ .reg .u64 t; cvta.to.shared.u64 t, %1; cvt.u32.u64 %0, t; }" : "=r"(a) : "l"(p));
    return a;
}

#define CP_ASYNC16(dst, src) \
    asm volatile("cp.async.cg.shared.global [%0], [%1], 16;" :: "r"(dst), "l"(src) : "memory")
#define CP_COMMIT() asm volatile("cp.async.commit_group;" ::: "memory")
#define CP_WAITG(n) asm volatile("cp.async.wait_group %0;" :: "n"(n) : "memory")

#define LDM4(r0, r1, r2, r3, addr) \
    asm volatile("ldmatrix.sync.aligned.m8n8.x4.shared.b16 {%0,%1,%2,%3}, [%4];" \
        : "=r"(r0), "=r"(r1), "=r"(r2), "=r"(r3) : "r"(addr))

#define MMA16816(d, a0, a1, a2, a3, b0, b1) \
    asm volatile("mma.sync.aligned.m16n8k16.row.col.f32.f16.f16.f32 " \
        "{%0,%1,%2,%3}, {%4,%5,%6,%7}, {%8,%9}, {%0,%1,%2,%3};" \
        : "+f"((d)[0]), "+f"((d)[1]), "+f"((d)[2]), "+f"((d)[3]) \
        : "r"(a0), "r"(a1), "r"(a2), "r"(a3), "r"(b0), "r"(b1))

// swizzled byte offset of 16B chunk (r, c), c in [0,16), 256 B rows
__device__ __forceinline__ uint32_t swz(int r, int c) {
    return (uint32_t)(r * 256 + ((c ^ (r & 7)) << 4));
}

// ===================== Kernel 1: W fp32 -> fp16 preconvert (tiny) =====================
__global__ void conv_kernel(const float* __restrict__ W)
{
    const int W4 = T_DIM * D_DIM * D_DIM / 4;   // 32768 float4
    int i = blockIdx.x * blockDim.x + threadIdx.x;
    if (i < W4) {
        float4 v = reinterpret_cast<const float4*>(W)[i];
        uint32_t hw[4];
        float vf[4] = {v.x, v.y, v.z, v.w};
#pragma unroll
        for (int e = 0; e < 4; e++)
            hw[e] = (uint32_t)__half_as_ushort(__float2half_rn(vf[e]));
        reinterpret_cast<uint2*>(g_whi)[i] =
            make_uint2(hw[0] | (hw[1] << 16), hw[2] | (hw[3] << 16));
    }
}

// ===================== Kernel 2: GEMM + gating + fold =====================
// Load W pair (t=2tp, 2tp+1): 2 tiles of 64 rows x 128 K-cols fp16 (16 KB each).
__device__ __forceinline__ void issue_w_pair(uint32_t sb, int buf, int tp, int nbase, int tid)
{
    const uint32_t dst0 = sb + OFF_W + (uint32_t)buf * 32768u;
#pragma unroll
    for (int k = 0; k < 8; k++) {
        int ci = tid + k * THREADS;              // 0..2047
        int tt = ci >> 10;                       // 0/1 within pair
        int li = ci & 1023;
        int r = li >> 4, c = li & 15;
        const size_t base = (size_t)(2 * tp + tt) * (D_DIM * D_DIM) + (size_t)nbase * D_DIM;
        CP_ASYNC16(dst0 + (uint32_t)tt * 16384u + swz(r, c),
                   g_whi + base + (size_t)r * D_DIM + c * 8);
    }
}

__global__ void __launch_bounds__(THREADS, 2)
dt_mma_kernel(const float* __restrict__ x,
              const float* __restrict__ b,
              const float* __restrict__ p,
              float* __restrict__ out)
{
    extern __shared__ char smem[];
    const uint32_t sb = smem_u32(smem);
    const int tid  = threadIdx.x;
    const int wid  = tid >> 5;
    const int lane = tid & 31;
    const int mblk = blockIdx.x >> 1;
    const int nblk = blockIdx.x & 1;
    const int row0 = mblk * MTILE;
    const int nbase = nblk * NTILE;

    float* s_p   = reinterpret_cast<float*>(smem + OFF_P);
    float* s_b   = reinterpret_cast<float*>(smem + OFF_B);
    float* s_sim = reinterpret_cast<float*>(smem + OFF_SIM);
    float* s_pn2 = reinterpret_cast<float*>(smem + OFF_PN2);

    // W pair ring prologue: pair0 -> buf0, pair1 -> buf1 (fly during convert+gating)
    issue_w_pair(sb, 0, 0, nbase, tid); CP_COMMIT();
    issue_w_pair(sb, 1, 1, nbase, tid); CP_COMMIT();

    // p (full) and b (this CTA's 64-col slice) to smem
#pragma unroll
    for (int i = tid; i < T_DIM * D_DIM; i += THREADS) s_p[i] = p[i];
#pragma unroll
    for (int i = tid; i < T_DIM * NTILE; i += THREADS)
        s_b[i] = b[(i >> 6) * D_DIM + nbase + (i & 63)];

    // x tile: fp32 gmem -> fp16 swizzled smem (2048 16B chunks, 8 per thread)
#pragma unroll
    for (int k = 0; k < 8; k++) {
        int ci = tid + k * THREADS;
        int r = ci >> 4, c = ci & 15;
        const float4* src = reinterpret_cast<const float4*>(
            x + (size_t)(row0 + r) * D_DIM + c * 8);
        float4 v0 = src[0], v1 = src[1];
        uint32_t hw[4];
        hw[0] = (uint32_t)__half_as_ushort(__float2half_rn(v0.x))
              | ((uint32_t)__half_as_ushort(__float2half_rn(v0.y)) << 16);
        hw[1] = (uint32_t)__half_as_ushort(__float2half_rn(v0.z))
              | ((uint32_t)__half_as_ushort(__float2half_rn(v0.w)) << 16);
        hw[2] = (uint32_t)__half_as_ushort(__float2half_rn(v1.x))
              | ((uint32_t)__half_as_ushort(__float2half_rn(v1.y)) << 16);
        hw[3] = (uint32_t)__half_as_ushort(__float2half_rn(v1.z))
              | ((uint32_t)__half_as_ushort(__float2half_rn(v1.w)) << 16);
        *reinterpret_cast<uint4*>(smem + OFF_X + swz(r, c)) =
            make_uint4(hw[0], hw[1], hw[2], hw[3]);
    }

    __syncthreads();   // s_p visible for gating

    // ---- Gating (exact fp32; overlaps W cp.async) ----
    if (tid < T_DIM) {
        float pn2 = 0.f;
        const float4* pr = reinterpret_cast<const float4*>(s_p + tid * D_DIM);
#pragma unroll 8
        for (int i = 0; i < 32; i++) {
            float4 pv = pr[i];
            pn2 += pv.x * pv.x + pv.y * pv.y + pv.z * pv.z + pv.w * pv.w;
        }
        s_pn2[tid] = pn2;
    }
    float dots[T_DIM], xn2 = 0.f;
    if (tid < MTILE) {
#pragma unroll
        for (int t = 0; t < T_DIM; t++) dots[t] = 0.f;
        const float4* xr = reinterpret_cast<const float4*>(x + (size_t)(row0 + tid) * D_DIM);
#pragma unroll 4
        for (int i = 0; i < 32; i++) {
            float4 v = xr[i];
            xn2 += v.x * v.x + v.y * v.y + v.z * v.z + v.w * v.w;
#pragma unroll
            for (int t = 0; t < T_DIM; t++) {
                float4 pv = *reinterpret_cast<const float4*>(s_p + t * D_DIM + i * 4);
                dots[t] += v.x * pv.x + v.y * pv.y + v.z * pv.z + v.w * pv.w;
            }
        }
    }
    __syncthreads();   // s_pn2 ready
    if (tid < MTILE) {
        float xn = sqrtf(xn2);
        float cosv[T_DIM], m = -1e30f;
#pragma unroll
        for (int t = 0; t < T_DIM; t++) {
            cosv[t] = dots[t] / (xn * sqrtf(s_pn2[t]));
            m = fmaxf(m, cosv[t]);
        }
        float ev[T_DIM], sum = 0.f;
#pragma unroll
        for (int t = 0; t < T_DIM; t++) { ev[t] = expf(cosv[t] - m); sum += ev[t]; }
        float inv = 1.f / sum;
#pragma unroll
        for (int t = 0; t < T_DIM; t++) s_sim[tid * 9 + t] = ev[t] * inv;
    }

    CP_WAITG(1);       // pair0 complete (pair1 may still be in flight)
    __syncthreads();   // x tile + pair0 + sim visible

    // ---- Warp tiling: 4(M) x 2(N) grid, warp tile 32x32 ----
    const int wm = wid & 3, wn = wid >> 2;
    const int mbw = wm * 32, nbw = wn * 32;

    const uint32_t arowb = (uint32_t)((mbw + (lane & 15)) * 256);
    const int     achnk  = lane >> 4;
    const uint32_t browb = (uint32_t)((nbw + (lane & 7) + ((lane >> 4) << 3)) * 256);
    const int     bchnk  = (lane >> 3) & 1;
    const int     bank   = lane & 7;
    const int rql = lane >> 2;
    const int cpl = (lane & 3) * 2;

    float acc[2][4][4];
#pragma unroll
    for (int i = 0; i < 2; i++)
#pragma unroll
        for (int j = 0; j < 4; j++)
#pragma unroll
            for (int e = 0; e < 4; e++) acc[i][j][e] = 0.f;

#pragma unroll 1
    for (int i = 0; i < 4; i++) {               // t-pair iterations: t = 2i, 2i+1
        const uint32_t wbuf = sb + OFF_W + (uint32_t)(i & 1) * 32768u;

        float y0[2][4][4], y1[2][4][4];
#pragma unroll
        for (int a = 0; a < 2; a++)
#pragma unroll
            for (int j = 0; j < 4; j++)
#pragma unroll
                for (int e = 0; e < 4; e++) { y0[a][j][e] = 0.f; y1[a][j][e] = 0.f; }

#pragma unroll
        for (int k = 0; k < 8; k++) {
            const uint32_t aoff = arowb + (uint32_t)((((2 * k + achnk) ^ bank)) << 4);
            const uint32_t boff = browb + (uint32_t)((((2 * k + bchnk) ^ bank)) << 4);

            uint32_t a0, a1, a2, a3, a4, a5, a6, a7;
            LDM4(a0, a1, a2, a3, sb + OFF_X + aoff);
            LDM4(a4, a5, a6, a7, sb + OFF_X + aoff + 16u * 256u);

            // t0: B from wbuf + 0
            {
                uint32_t b0, b1, b2, b3, b4, b5, b6, b7;
                LDM4(b0, b1, b2, b3, wbuf + boff);
                LDM4(b4, b5, b6, b7, wbuf + boff + 16u * 256u);
                MMA16816(y0[0][0], a0, a1, a2, a3, b0, b1);
                MMA16816(y0[0][1], a0, a1, a2, a3, b2, b3);
                MMA16816(y0[0][2], a0, a1, a2, a3, b4, b5);
                MMA16816(y0[0][3], a0, a1, a2, a3, b6, b7);
                MMA16816(y0[1][0], a4, a5, a6, a7, b0, b1);
                MMA16816(y0[1][1], a4, a5, a6, a7, b2, b3);
                MMA16816(y0[1][2], a4, a5, a6, a7, b4, b5);
                MMA16816(y0[1][3], a4, a5, a6, a7, b6, b7);
            }
            // t1: B from wbuf + 16384
            {
                uint32_t b0, b1, b2, b3, b4, b5, b6, b7;
                LDM4(b0, b1, b2, b3, wbuf + 16384u + boff);
                LDM4(b4, b5, b6, b7, wbuf + 16384u + boff + 16u * 256u);
                MMA16816(y1[0][0], a0, a1, a2, a3, b0, b1);
                MMA16816(y1[0][1], a0, a1, a2, a3, b2, b3);
                MMA16816(y1[0][2], a0, a1, a2, a3, b4, b5);
                MMA16816(y1[0][3], a0, a1, a2, a3, b6, b7);
                MMA16816(y1[1][0], a4, a5, a6, a7, b0, b1);
                MMA16816(y1[1][1], a4, a5, a6, a7, b2, b3);
                MMA16816(y1[1][2], a4, a5, a6, a7, b4, b5);
                MMA16816(y1[1][3], a4, a5, a6, a7, b6, b7);
            }
        }

        // fold both transforms of the pair
        const int t0 = 2 * i, t1 = 2 * i + 1;
#pragma unroll
        for (int mt = 0; mt < 2; mt++) {
            const int rloc = mbw + mt * 16 + rql;
            const float s00 = s_sim[rloc * 9 + t0];
            const float s01 = s_sim[(rloc + 8) * 9 + t0];
            const float s10 = s_sim[rloc * 9 + t1];
            const float s11 = s_sim[(rloc + 8) * 9 + t1];
#pragma unroll
            for (int nt = 0; nt < 4; nt++) {
                const int c = nbw + nt * 8 + cpl;
                const float b00 = s_b[t0 * NTILE + c];
                const float b01 = s_b[t0 * NTILE + c + 1];
                const float b10 = s_b[t1 * NTILE + c];
                const float b11 = s_b[t1 * NTILE + c + 1];
                acc[mt][nt][0] = fmaf(s00, y0[mt][nt][0] + b00, acc[mt][nt][0]);
                acc[mt][nt][1] = fmaf(s00, y0[mt][nt][1] + b01, acc[mt][nt][1]);
                acc[mt][nt][2] = fmaf(s01, y0[mt][nt][2] + b00, acc[mt][nt][2]);
                acc[mt][nt][3] = fmaf(s01, y0[mt][nt][3] + b01, acc[mt][nt][3]);
                acc[mt][nt][0] = fmaf(s10, y1[mt][nt][0] + b10, acc[mt][nt][0]);
                acc[mt][nt][1] = fmaf(s10, y1[mt][nt][1] + b11, acc[mt][nt][1]);
                acc[mt][nt][2] = fmaf(s11, y1[mt][nt][2] + b10, acc[mt][nt][2]);
                acc[mt][nt][3] = fmaf(s11, y1[mt][nt][3] + b11, acc[mt][nt][3]);
            }
        }

        // refill: pair i+2 into the buffer we just consumed
        if (i < 2) {
            __syncthreads();
            issue_w_pair(sb, i & 1, i + 2, nbase, tid);
            CP_COMMIT();
        }
        if (i < 3) {
            if (i < 2) { CP_WAITG(1); } else { CP_WAITG(0); }
            __syncthreads();
        }
    }

    // ---- Epilogue: residual (exact fp32 x from gmem) + store ----
#pragma unroll
    for (int mt = 0; mt < 2; mt++) {
        const int rg0 = row0 + mbw + mt * 16 + rql;
        const int rg1 = rg0 + 8;
#pragma unroll
        for (int nt = 0; nt < 4; nt++) {
            const int c = nbase + nbw + nt * 8 + cpl;
            float2 xv0 = *reinterpret_cast<const float2*>(x + (size_t)rg0 * D_DIM + c);
            float2 o0  = make_float2(acc[mt][nt][0] + xv0.x, acc[mt][nt][1] + xv0.y);
            *reinterpret_cast<float2*>(out + (size_t)rg0 * D_DIM + c) = o0;
            float2 xv1 = *reinterpret_cast<const float2*>(x + (size_t)rg1 * D_DIM + c);
            float2 o1  = make_float2(acc[mt][nt][2] + xv1.x, acc[mt][nt][3] + xv1.y);
            *reinterpret_cast<float2*>(out + (size_t)rg1 * D_DIM + c) = o1;
        }
    }
}

extern "C" void kernel_launch(void* const* d_in, const int* in_sizes, int n_in,
                              void* d_out, int out_size)
{
    (void)n_in; (void)out_size;
    const float* x = (const float*)d_in[0];   // [B,S,D]
    const float* W = (const float*)d_in[1];   // [T,D,D]
    const float* b = (const float*)d_in[2];   // [T,D]
    const float* p = (const float*)d_in[3];   // [T,1,D]
    float* out = (float*)d_out;

    const int nrows = in_sizes[0] / D_DIM;    // 65536
    const int grid  = (nrows / MTILE) * 2;    // 1024

    conv_kernel<<<128, 256>>>(W);

    cudaFuncSetAttribute(dt_mma_kernel,
                         cudaFuncAttributeMaxDynamicSharedMemorySize, SMEM_TOTAL);
    dt_mma_kernel<<<grid, THREADS, SMEM_TOTAL>>>(x, b, p, out);
}